// round 1
// baseline (speedup 1.0000x reference)
#include <cuda_runtime.h>
#include <cstddef>

// ---------------------------------------------------------------------------
// PoseNetX_LIGHT: conv7x7/s16 -> relu -> avgpool -> fc -> {node head, edge head}
// Edge GEMM algebraically factored:  edge = relu(A1[n1] + A2[n2]),
//   A1 = node @ W1^T + proj_b,  A2 = node @ W2^T   (proj_w = [W1 | W2])
// ---------------------------------------------------------------------------

#define NN 256        // nodes
#define NE 8192       // edges
#define CI 3
#define HW 256
#define CO 512
#define KK 147        // 3*7*7
#define FEAT 2048

// -------- scratch (no allocations allowed) --------
__device__ float g_wT[KK * CO];          // transposed conv weights [k][co]
__device__ float g_feat[NN * CO];        // pooled features
__device__ float g_node[NN * FEAT];      // fc output (pre-relu)
__device__ float g_A1[NN * FEAT];        // node @ W1^T + proj_b
__device__ float g_A2[NN * FEAT];        // node @ W2^T
__device__ int   g_n1[NE];
__device__ int   g_n2[NE];

// -------- packed f32x2 helpers --------
__device__ __forceinline__ unsigned long long pk2(float x, float y) {
    unsigned long long r;
    asm("mov.b64 %0, {%1, %2};" : "=l"(r)
        : "r"(__float_as_uint(x)), "r"(__float_as_uint(y)));
    return r;
}
__device__ __forceinline__ void upk2(unsigned long long v, float& x, float& y) {
    unsigned a, b;
    asm("mov.b64 {%0, %1}, %2;" : "=r"(a), "=r"(b) : "l"(v));
    x = __uint_as_float(a);
    y = __uint_as_float(b);
}
__device__ __forceinline__ void fma2(unsigned long long& d,
                                     unsigned long long a, unsigned long long b) {
    asm("fma.rn.f32x2 %0, %1, %2, %0;" : "+l"(d) : "l"(a), "l"(b));
}

// ---------------------------------------------------------------------------
// K0: normalize edge_index (auto-detect int32 vs int64), n1=min, n2=max
// ---------------------------------------------------------------------------
__global__ void edge_prep_kernel(const void* __restrict__ ei_raw) {
    __shared__ int nz;
    int tid = threadIdx.x;
    if (tid == 0) nz = 0;
    __syncthreads();
    const int* w32 = (const int*)ei_raw;
    // if dtype is int64 (values < 2^31, nonneg), every odd 32-bit word is 0
    if (tid < 64 && w32[2 * tid + 1] != 0) atomicOr(&nz, 1);
    __syncthreads();
    if (nz == 0) {
        const long long* e = (const long long*)ei_raw;
        for (int i = tid; i < NE; i += 256) {
            int u = (int)e[i], v = (int)e[NE + i];
            g_n1[i] = min(u, v);
            g_n2[i] = max(u, v);
        }
    } else {
        const int* e = w32;
        for (int i = tid; i < NE; i += 256) {
            int u = e[i], v = e[NE + i];
            g_n1[i] = min(u, v);
            g_n2[i] = max(u, v);
        }
    }
}

// ---------------------------------------------------------------------------
// K1: transpose conv weights [CO][3][7][7] -> [k=147][CO]
// ---------------------------------------------------------------------------
__global__ void wt_kernel(const float* __restrict__ conv_w) {
    int idx = blockIdx.x * 256 + threadIdx.x;
    if (idx < CO * KK) {
        int co = idx / KK;
        int k  = idx - co * KK;
        g_wT[k * CO + co] = conv_w[idx];
    }
}

// ---------------------------------------------------------------------------
// K2: direct conv + bias + relu + global-average-pool, fused.
// grid (4, 256): blockIdx.x = 128-channel group, blockIdx.y = node.
// block 128 threads = 16 channel-lanes x 8 position-rows.
// thread tile: 4 channel-pairs (f32x2, LDS.64 from smem weights) x 4 positions.
// dyn smem: Ws[147][128] weights + Pt[147][32] patch = 94080 B.
// ---------------------------------------------------------------------------
__global__ void conv_pool_kernel(const float* __restrict__ x,
                                 const float* __restrict__ cbias) {
    extern __shared__ __align__(16) float sm[];
    float* Ws = sm;                // [147][128]
    float* Pt = sm + KK * 128;     // [147][32], reused for reduction

    const int tid   = threadIdx.x;     // 0..127
    const int clane = tid & 15;        // 0..15
    const int pr    = tid >> 4;        // 0..7
    const int cb    = blockIdx.x;      // 0..3
    const int n     = blockIdx.y;      // 0..255
    const int cbase = cb * 128;

    // stage weights for this channel group
    for (int idx = tid; idx < KK * 128; idx += 128) {
        int k = idx >> 7, c = idx & 127;
        Ws[idx] = g_wT[k * CO + cbase + c];
    }

    float bx[4], by[4];
#pragma unroll
    for (int j = 0; j < 4; j++) {
        int c = cbase + clane * 2 + 32 * j;
        bx[j] = cbias[c];
        by[j] = cbias[c + 1];
    }

    float pool[4][2];
#pragma unroll
    for (int j = 0; j < 4; j++) { pool[j][0] = 0.f; pool[j][1] = 0.f; }

    const float* xb = x + (size_t)n * (CI * HW * HW);

    for (int chunk = 0; chunk < 8; chunk++) {
        __syncthreads();
        // stage 32 position patches: Pt[k][p]
        for (int idx = tid; idx < KK * 32; idx += 128) {
            int k = idx >> 5, p = idx & 31;
            int ci = k / 49;
            int r  = k - ci * 49;
            int ky = r / 7;
            int kx = r - ky * 7;
            int pos = chunk * 32 + p;
            int oy = pos >> 4, ox = pos & 15;
            int iy = oy * 16 - 3 + ky;
            int ix = ox * 16 - 3 + kx;
            float v = 0.f;
            if ((unsigned)iy < 256u && (unsigned)ix < 256u)
                v = xb[ci * 65536 + iy * 256 + ix];
            Pt[idx] = v;
        }
        __syncthreads();

        unsigned long long acc[4][4];
#pragma unroll
        for (int j = 0; j < 4; j++)
#pragma unroll
            for (int t = 0; t < 4; t++) acc[j][t] = 0ull;

#pragma unroll 7
        for (int kk = 0; kk < KK; kk++) {
            unsigned long long wp[4];
#pragma unroll
            for (int j = 0; j < 4; j++)
                wp[j] = *(const unsigned long long*)&Ws[kk * 128 + clane * 2 + 32 * j];
#pragma unroll
            for (int t = 0; t < 4; t++) {
                float pv = Pt[kk * 32 + pr * 4 + t];
                unsigned long long pp = pk2(pv, pv);
#pragma unroll
                for (int j = 0; j < 4; j++) fma2(acc[j][t], wp[j], pp);
            }
        }

        // bias + relu + pool-accumulate
#pragma unroll
        for (int j = 0; j < 4; j++)
#pragma unroll
            for (int t = 0; t < 4; t++) {
                float sx, sy;
                upk2(acc[j][t], sx, sy);
                pool[j][0] += fmaxf(sx + bx[j], 0.f);
                pool[j][1] += fmaxf(sy + by[j], 0.f);
            }
    }

    __syncthreads();   // everyone done reading Pt
    // reduce the 8 position-rows per channel (reuse Pt as red[8][128])
#pragma unroll
    for (int j = 0; j < 4; j++) {
        int c = clane * 2 + 32 * j;
        Pt[pr * 128 + c]     = pool[j][0];
        Pt[pr * 128 + c + 1] = pool[j][1];
    }
    __syncthreads();
    {
        float s = 0.f;
#pragma unroll
        for (int p = 0; p < 8; p++) s += Pt[p * 128 + tid];
        g_feat[n * CO + cbase + tid] = s * (1.0f / 256.0f);
    }
}

// ---------------------------------------------------------------------------
// K3: NT GEMM  C[M,N] = A[M,K] @ B[N,K]^T (+bias[n]), fp32 via f32x2.
// 64x64 tile, BK=16, 256 threads, thread tile 4m x 2 n-pairs.
// M, N multiples of 64; K multiple of 16 (true for all three calls).
// ---------------------------------------------------------------------------
__global__ void gemm_nt_kernel(const float* __restrict__ A, int lda,
                               const float* __restrict__ B, int ldb,
                               const float* __restrict__ bias,
                               float* __restrict__ C, int ldc, int K) {
    __shared__ __align__(16) float As[16 * 65];
    __shared__ __align__(16) float Bs[16 * 66];
    const int tid = threadIdx.x;        // 0..255
    const int nl  = tid & 15;           // 0..15
    const int mr  = tid >> 4;           // 0..15
    const int m0  = blockIdx.y * 64;
    const int n0  = blockIdx.x * 64;

    unsigned long long acc[4][2];
#pragma unroll
    for (int i = 0; i < 4; i++) { acc[i][0] = 0ull; acc[i][1] = 0ull; }

    for (int k0 = 0; k0 < K; k0 += 16) {
#pragma unroll
        for (int i = 0; i < 4; i++) {
            int row = mr + 16 * i;  // tile row loaded by this thread
            As[nl * 65 + row] = A[(size_t)(m0 + row) * lda + k0 + nl];
            Bs[nl * 66 + row] = B[(size_t)(n0 + row) * ldb + k0 + nl];
        }
        __syncthreads();
#pragma unroll
        for (int kk = 0; kk < 16; kk++) {
            unsigned long long bp0 = *(const unsigned long long*)&Bs[kk * 66 + nl * 2];
            unsigned long long bp1 = *(const unsigned long long*)&Bs[kk * 66 + nl * 2 + 32];
#pragma unroll
            for (int i = 0; i < 4; i++) {
                float a = As[kk * 65 + mr + 16 * i];
                unsigned long long ap = pk2(a, a);
                fma2(acc[i][0], ap, bp0);
                fma2(acc[i][1], ap, bp1);
            }
        }
        __syncthreads();
    }

#pragma unroll
    for (int i = 0; i < 4; i++) {
        int m = m0 + mr + 16 * i;
#pragma unroll
        for (int q = 0; q < 2; q++) {
            int nc = n0 + nl * 2 + 32 * q;
            float vx, vy;
            upk2(acc[i][q], vx, vy);
            if (bias) { vx += bias[nc]; vy += bias[nc + 1]; }
            C[(size_t)m * ldc + nc]     = vx;
            C[(size_t)m * ldc + nc + 1] = vy;
        }
    }
}

// ---------------------------------------------------------------------------
// K4: edge head. One warp per edge: v = relu(A1[n1]+A2[n2]); 6 dots + bias.
// ---------------------------------------------------------------------------
__global__ void edge_out_kernel(const float* __restrict__ xyzRw,
                                const float* __restrict__ xyzRb,
                                const float* __restrict__ wpqrRw,
                                const float* __restrict__ wpqrRb,
                                float* __restrict__ out) {
    int warp = (blockIdx.x * blockDim.x + threadIdx.x) >> 5;
    int lane = threadIdx.x & 31;
    if (warp >= NE) return;
    const float* r1 = g_A1 + (size_t)g_n1[warp] * FEAT;
    const float* r2 = g_A2 + (size_t)g_n2[warp] * FEAT;
    float acc[6] = {0.f, 0.f, 0.f, 0.f, 0.f, 0.f};
    for (int k = lane; k < FEAT; k += 32) {
        float v = fmaxf(r1[k] + r2[k], 0.f);
        acc[0] += v * __ldg(&xyzRw[k]);
        acc[1] += v * __ldg(&xyzRw[FEAT + k]);
        acc[2] += v * __ldg(&xyzRw[2 * FEAT + k]);
        acc[3] += v * __ldg(&wpqrRw[k]);
        acc[4] += v * __ldg(&wpqrRw[FEAT + k]);
        acc[5] += v * __ldg(&wpqrRw[2 * FEAT + k]);
    }
#pragma unroll
    for (int j = 0; j < 6; j++)
#pragma unroll
        for (int off = 16; off; off >>= 1)
            acc[j] += __shfl_xor_sync(0xffffffffu, acc[j], off);
    if (lane < 6) {
        float b = (lane < 3) ? xyzRb[lane] : wpqrRb[lane - 3];
        out[NN * 6 + warp * 6 + lane] = acc[lane] + b;
    }
}

// ---------------------------------------------------------------------------
// K5: node head. One warp per node on relu(g_node).
// ---------------------------------------------------------------------------
__global__ void node_out_kernel(const float* __restrict__ xyzw,
                                const float* __restrict__ xyzb,
                                const float* __restrict__ wpqrw,
                                const float* __restrict__ wpqrb,
                                float* __restrict__ out) {
    int warp = (blockIdx.x * blockDim.x + threadIdx.x) >> 5;
    int lane = threadIdx.x & 31;
    if (warp >= NN) return;
    const float* r = g_node + (size_t)warp * FEAT;
    float acc[6] = {0.f, 0.f, 0.f, 0.f, 0.f, 0.f};
    for (int k = lane; k < FEAT; k += 32) {
        float v = fmaxf(r[k], 0.f);
        acc[0] += v * __ldg(&xyzw[k]);
        acc[1] += v * __ldg(&xyzw[FEAT + k]);
        acc[2] += v * __ldg(&xyzw[2 * FEAT + k]);
        acc[3] += v * __ldg(&wpqrw[k]);
        acc[4] += v * __ldg(&wpqrw[FEAT + k]);
        acc[5] += v * __ldg(&wpqrw[2 * FEAT + k]);
    }
#pragma unroll
    for (int j = 0; j < 6; j++)
#pragma unroll
        for (int off = 16; off; off >>= 1)
            acc[j] += __shfl_xor_sync(0xffffffffu, acc[j], off);
    if (lane < 6) {
        float b = (lane < 3) ? xyzb[lane] : wpqrb[lane - 3];
        out[warp * 6 + lane] = acc[lane] + b;
    }
}

// ---------------------------------------------------------------------------
extern "C" void kernel_launch(void* const* d_in, const int* in_sizes, int n_in,
                              void* d_out, int out_size) {
    const float* x        = (const float*)d_in[0];
    const void*  ei       = d_in[1];
    const float* conv_w   = (const float*)d_in[2];
    const float* conv_b   = (const float*)d_in[3];
    const float* fc_w     = (const float*)d_in[4];
    const float* fc_b     = (const float*)d_in[5];
    const float* proj_w   = (const float*)d_in[6];
    const float* proj_b   = (const float*)d_in[7];
    const float* xyz_w    = (const float*)d_in[8];
    const float* xyz_b    = (const float*)d_in[9];
    const float* wpqr_w   = (const float*)d_in[10];
    const float* wpqr_b   = (const float*)d_in[11];
    const float* xyz_R_w  = (const float*)d_in[12];
    const float* xyz_R_b  = (const float*)d_in[13];
    const float* wpqr_R_w = (const float*)d_in[14];
    const float* wpqr_R_b = (const float*)d_in[15];
    float* out = (float*)d_out;

    float *pfeat, *pnode, *pA1, *pA2;
    cudaGetSymbolAddress((void**)&pfeat, g_feat);
    cudaGetSymbolAddress((void**)&pnode, g_node);
    cudaGetSymbolAddress((void**)&pA1, g_A1);
    cudaGetSymbolAddress((void**)&pA2, g_A2);

    edge_prep_kernel<<<1, 256>>>(ei);
    wt_kernel<<<(CO * KK + 255) / 256, 256>>>(conv_w);

    const int conv_smem = (KK * 128 + KK * 32) * 4;  // 94080 B
    cudaFuncSetAttribute(conv_pool_kernel,
                         cudaFuncAttributeMaxDynamicSharedMemorySize, conv_smem);
    conv_pool_kernel<<<dim3(4, NN), 128, conv_smem>>>(x, conv_b);

    // fc: node[256,2048] = feat[256,512] @ fc_w[2048,512]^T + fc_b
    gemm_nt_kernel<<<dim3(FEAT / 64, NN / 64), 256>>>(pfeat, CO, fc_w, CO, fc_b,
                                                      pnode, FEAT, CO);
    // A1 = node @ W1^T + proj_b ; A2 = node @ W2^T
    gemm_nt_kernel<<<dim3(FEAT / 64, NN / 64), 256>>>(pnode, FEAT, proj_w, 2 * FEAT,
                                                      proj_b, pA1, FEAT, FEAT);
    gemm_nt_kernel<<<dim3(FEAT / 64, NN / 64), 256>>>(pnode, FEAT, proj_w + FEAT,
                                                      2 * FEAT, nullptr, pA2, FEAT, FEAT);

    edge_out_kernel<<<(NE * 32) / 256, 256>>>(xyz_R_w, xyz_R_b, wpqr_R_w, wpqr_R_b, out);
    node_out_kernel<<<(NN * 32) / 256, 256>>>(xyz_w, xyz_b, wpqr_w, wpqr_b, out);
}